// round 1
// baseline (speedup 1.0000x reference)
#include <cuda_runtime.h>

#define YD 384
#define XD 512
#define LD 32
#define EPSR 1e-4f

__global__ __launch_bounds__(256) void quadfit_kernel(
    const float* __restrict__ feat0,
    const float* __restrict__ feat1,
    const float* __restrict__ flow,
    float* __restrict__ out)
{
    __shared__ float c_s[256 * 9];
    const int w    = threadIdx.x >> 5;
    const int lane = threadIdx.x & 31;
    const int base = blockIdx.x * 256;

    // ---------------- Phase A: warp-per-pixel cost computation ----------------
    for (int it = 0; it < 32; ++it) {
        const int li = it * 8 + w;       // local pixel in block
        const int p  = base + li;        // linear pixel
        const int pyi = p >> 9;          // X = 512
        const int pxi = p & 511;

        const float u = flow[p * 3 + 0];
        const float v = flow[p * 3 + 1];
        const float px = (float)pxi + u;
        const float py = (float)pyi + v;
        const float bxf = floorf(px), byf = floorf(py);
        const float wx = px - bxf, wy = py - byf;
        const int bx = (int)bxf, by = (int)byf;

        const float f0 = feat0[p * LD + lane];

        float c[9];
        const bool interior = (bx >= 1) && (bx <= XD - 3) && (by >= 1) && (by <= YD - 3);
        if (interior) {
            // 4x4 patch rows by-1..by+2, cols bx-1..bx+2; shared (wx,wy)
            float h[4][3];
            const float* rp = feat1 + ((size_t)(by - 1) * XD + (bx - 1)) * LD + lane;
#pragma unroll
            for (int r = 0; r < 4; r++) {
                const float* q = rp + r * (XD * LD);
                float p0 = __ldg(q + 0 * LD);
                float p1 = __ldg(q + 1 * LD);
                float p2 = __ldg(q + 2 * LD);
                float p3 = __ldg(q + 3 * LD);
                h[r][0] = p0 + wx * (p1 - p0);
                h[r][1] = p1 + wx * (p2 - p1);
                h[r][2] = p2 + wx * (p3 - p2);
            }
#pragma unroll
            for (int k = 0; k < 9; k++) {
                const int r = k / 3, cc = k % 3;
                float val = h[r][cc] + wy * (h[r + 1][cc] - h[r][cc]);
                float d = f0 - val;
                c[k] = d * d;
            }
        } else {
            // exact clamped path (matches reference: x1 = clip(clip(x0)+1))
#pragma unroll
            for (int k = 0; k < 9; k++) {
                const int ox = k % 3 - 1, oy = k / 3 - 1;
                int x0 = min(max(bx + ox, 0), XD - 1);
                int x1 = min(x0 + 1, XD - 1);
                int y0 = min(max(by + oy, 0), YD - 1);
                int y1 = min(y0 + 1, YD - 1);
                float f00 = __ldg(feat1 + ((size_t)y0 * XD + x0) * LD + lane);
                float f01 = __ldg(feat1 + ((size_t)y0 * XD + x1) * LD + lane);
                float f10 = __ldg(feat1 + ((size_t)y1 * XD + x0) * LD + lane);
                float f11 = __ldg(feat1 + ((size_t)y1 * XD + x1) * LD + lane);
                float top = f00 + wx * (f01 - f00);
                float bot = f10 + wx * (f11 - f10);
                float val = top + wy * (bot - top);
                float d = f0 - val;
                c[k] = d * d;
            }
        }

        // butterfly reduce each of the 9 costs across 32 channels
#pragma unroll
        for (int k = 0; k < 9; k++) {
            float vr = c[k];
            vr += __shfl_xor_sync(0xffffffffu, vr, 16);
            vr += __shfl_xor_sync(0xffffffffu, vr, 8);
            vr += __shfl_xor_sync(0xffffffffu, vr, 4);
            vr += __shfl_xor_sync(0xffffffffu, vr, 2);
            vr += __shfl_xor_sync(0xffffffffu, vr, 1);
            c[k] = vr;
        }
        if (lane == 0) {
#pragma unroll
            for (int k = 0; k < 9; k++) c_s[li * 9 + k] = c[k];
        }
    }

    __syncthreads();

    // ---------------- Phase B: thread-per-pixel softmax + 6x6 solve ----------------
    {
        const int t = threadIdx.x;
        const int p = base + t;

        float c[9];
#pragma unroll
        for (int k = 0; k < 9; k++) c[k] = c_s[t * 9 + k];

        // softmax(-c): weights
        float m = c[0];
#pragma unroll
        for (int k = 1; k < 9; k++) m = fminf(m, c[k]);
        float wgt[9];
        float s = 0.f;
#pragma unroll
        for (int k = 0; k < 9; k++) { wgt[k] = __expf(m - c[k]); s += wgt[k]; }
        const float inv_s = 1.f / s;
#pragma unroll
        for (int k = 0; k < 9; k++) wgt[k] *= inv_s;

        // Build AtWA (lower triangle, idx(i,j)=i*(i+1)/2+j) and rhs.
        float M[21];
        float r6[6];
#pragma unroll
        for (int i = 0; i < 21; i++) M[i] = 0.f;
#pragma unroll
        for (int i = 0; i < 6; i++) r6[i] = 0.f;
#pragma unroll
        for (int k = 0; k < 9; k++) {
            const float ox = (float)(k % 3 - 1);
            const float oy = (float)(k / 3 - 1);
            const float a[6] = {ox * ox, oy * oy, ox * oy, ox, oy, 1.f};
            const float wk = wgt[k];
            const float wc = wk * c[k];
            int idx = 0;
#pragma unroll
            for (int i = 0; i < 6; i++) {
                r6[i] += a[i] * wc;
#pragma unroll
                for (int j = 0; j <= i; j++) { M[idx] += a[i] * a[j] * wk; idx++; }
            }
        }
        // + EPS * I
        M[0] += EPSR; M[2] += EPSR; M[5] += EPSR; M[9] += EPSR; M[14] += EPSR; M[20] += EPSR;

        // Cholesky factorization (SPD by construction)
        float Lm[21];
        float invd[6];
#pragma unroll
        for (int j = 0; j < 6; j++) {
            float d = M[j * (j + 1) / 2 + j];
#pragma unroll
            for (int k2 = 0; k2 < j; k2++) { float l = Lm[j * (j + 1) / 2 + k2]; d -= l * l; }
            const float iv = rsqrtf(d);
            invd[j] = iv;
            Lm[j * (j + 1) / 2 + j] = d * iv;
#pragma unroll
            for (int i = j + 1; i < 6; i++) {
                float sij = M[i * (i + 1) / 2 + j];
#pragma unroll
                for (int k2 = 0; k2 < j; k2++)
                    sij -= Lm[i * (i + 1) / 2 + k2] * Lm[j * (j + 1) / 2 + k2];
                Lm[i * (i + 1) / 2 + j] = sij * iv;
            }
        }
        // forward substitution: L y = rhs
        float yv[6];
#pragma unroll
        for (int i = 0; i < 6; i++) {
            float s2 = r6[i];
#pragma unroll
            for (int k2 = 0; k2 < i; k2++) s2 -= Lm[i * (i + 1) / 2 + k2] * yv[k2];
            yv[i] = s2 * invd[i];
        }
        // back substitution: L^T x = y
        float xv[6];
#pragma unroll
        for (int i = 5; i >= 0; i--) {
            float s2 = yv[i];
#pragma unroll
            for (int k2 = i + 1; k2 < 6; k2++) s2 -= Lm[k2 * (k2 + 1) / 2 + i] * xv[k2];
            xv[i] = s2 * invd[i];
        }

        // p*6 floats is 8-byte aligned -> 3x float2 stores
        float2* op = reinterpret_cast<float2*>(out + (size_t)p * 6);
        op[0] = make_float2(xv[0], xv[1]);
        op[1] = make_float2(xv[2], xv[3]);
        op[2] = make_float2(xv[4], xv[5]);
    }
}

extern "C" void kernel_launch(void* const* d_in, const int* in_sizes, int n_in,
                              void* d_out, int out_size)
{
    const float* feat0 = (const float*)d_in[0];
    const float* feat1 = (const float*)d_in[1];
    const float* flow  = (const float*)d_in[2];
    float* out = (float*)d_out;
    // Y*X = 196608 pixels, 256 pixels per block
    quadfit_kernel<<<(YD * XD) / 256, 256>>>(feat0, feat1, flow, out);
}

// round 2
// speedup vs baseline: 1.8345x; 1.8345x over previous
#include <cuda_runtime.h>

#define YD 384
#define XD 512
#define LD 32
#define EPSR 1e-4f

__global__ __launch_bounds__(256) void quadfit_kernel(
    const float* __restrict__ feat0,
    const float* __restrict__ feat1,
    const float* __restrict__ flow,
    float* __restrict__ out)
{
    __shared__ float c_s[256 * 9];
    const int w    = threadIdx.x >> 5;   // warp 0..7
    const int lane = threadIdx.x & 31;
    const int g    = lane >> 3;          // pixel group within warp 0..3
    const int s    = lane & 7;           // sublane = float4 channel slot 0..7
    const int base = blockIdx.x * 256;

    const float4* __restrict__ f0v = (const float4*)feat0;
    const float4* __restrict__ f1v = (const float4*)feat1;

    // ---------------- Phase A: 4 pixels per warp, 8 lanes (float4) per pixel ----------------
    for (int it = 0; it < 8; ++it) {
        const int li  = it * 32 + w * 4 + g;  // local pixel in block
        const int p   = base + li;            // linear pixel
        const int pyi = p >> 9;               // X = 512
        const int pxi = p & 511;

        const float u = flow[p * 3 + 0];
        const float v = flow[p * 3 + 1];
        const float px = (float)pxi + u;
        const float py = (float)pyi + v;
        const float bxf = floorf(px), byf = floorf(py);
        const float wx = px - bxf, wy = py - byf;
        const int bx = (int)bxf, by = (int)byf;

        const float4 f0 = f0v[p * 8 + s];

        float c[9];
        const bool interior = (bx >= 1) && (bx <= XD - 3) && (by >= 1) && (by <= YD - 3);
        if (interior) {
            // stream 4 rows of the 4x4 patch; keep only two rows of horizontal lerps
            const float4* rp = f1v + ((size_t)(by - 1) * XD + (bx - 1)) * 8 + s;
            float4 hp0, hp1, hp2;   // previous row horizontal lerps
            {
                float4 p0 = __ldg(rp + 0);
                float4 p1 = __ldg(rp + 8);
                float4 p2 = __ldg(rp + 16);
                float4 p3 = __ldg(rp + 24);
                hp0.x = p0.x + wx * (p1.x - p0.x); hp0.y = p0.y + wx * (p1.y - p0.y);
                hp0.z = p0.z + wx * (p1.z - p0.z); hp0.w = p0.w + wx * (p1.w - p0.w);
                hp1.x = p1.x + wx * (p2.x - p1.x); hp1.y = p1.y + wx * (p2.y - p1.y);
                hp1.z = p1.z + wx * (p2.z - p1.z); hp1.w = p1.w + wx * (p2.w - p1.w);
                hp2.x = p2.x + wx * (p3.x - p2.x); hp2.y = p2.y + wx * (p3.y - p2.y);
                hp2.z = p2.z + wx * (p3.z - p2.z); hp2.w = p2.w + wx * (p3.w - p2.w);
            }
#pragma unroll
            for (int r = 1; r < 4; r++) {
                const float4* q = rp + r * (XD * 8);
                float4 p0 = __ldg(q + 0);
                float4 p1 = __ldg(q + 8);
                float4 p2 = __ldg(q + 16);
                float4 p3 = __ldg(q + 24);
                float4 hc0, hc1, hc2;
                hc0.x = p0.x + wx * (p1.x - p0.x); hc0.y = p0.y + wx * (p1.y - p0.y);
                hc0.z = p0.z + wx * (p1.z - p0.z); hc0.w = p0.w + wx * (p1.w - p0.w);
                hc1.x = p1.x + wx * (p2.x - p1.x); hc1.y = p1.y + wx * (p2.y - p1.y);
                hc1.z = p1.z + wx * (p2.z - p1.z); hc1.w = p1.w + wx * (p2.w - p1.w);
                hc2.x = p2.x + wx * (p3.x - p2.x); hc2.y = p2.y + wx * (p3.y - p2.y);
                hc2.z = p2.z + wx * (p3.z - p2.z); hc2.w = p2.w + wx * (p3.w - p2.w);
                // vertical lerps between prev row and this row -> 3 cost samples
#pragma unroll
                for (int cc = 0; cc < 3; cc++) {
                    const float4 hp = (cc == 0) ? hp0 : (cc == 1) ? hp1 : hp2;
                    const float4 hc = (cc == 0) ? hc0 : (cc == 1) ? hc1 : hc2;
                    float vx = hp.x + wy * (hc.x - hp.x);
                    float vy = hp.y + wy * (hc.y - hp.y);
                    float vz = hp.z + wy * (hc.z - hp.z);
                    float vw = hp.w + wy * (hc.w - hp.w);
                    float dx = f0.x - vx, dy = f0.y - vy, dz = f0.z - vz, dw = f0.w - vw;
                    c[(r - 1) * 3 + cc] = dx * dx + dy * dy + dz * dz + dw * dw;
                }
                hp0 = hc0; hp1 = hc1; hp2 = hc2;
            }
        } else {
            // exact clamped path (matches reference: x1 = clip(clip(x0)+1))
#pragma unroll
            for (int k = 0; k < 9; k++) {
                const int ox = k % 3 - 1, oy = k / 3 - 1;
                int x0 = min(max(bx + ox, 0), XD - 1);
                int x1 = min(x0 + 1, XD - 1);
                int y0 = min(max(by + oy, 0), YD - 1);
                int y1 = min(y0 + 1, YD - 1);
                float4 f00 = __ldg(f1v + ((size_t)y0 * XD + x0) * 8 + s);
                float4 f01 = __ldg(f1v + ((size_t)y0 * XD + x1) * 8 + s);
                float4 f10 = __ldg(f1v + ((size_t)y1 * XD + x0) * 8 + s);
                float4 f11 = __ldg(f1v + ((size_t)y1 * XD + x1) * 8 + s);
                float tx = f00.x + wx * (f01.x - f00.x);
                float ty = f00.y + wx * (f01.y - f00.y);
                float tz = f00.z + wx * (f01.z - f00.z);
                float tw = f00.w + wx * (f01.w - f00.w);
                float bxv = f10.x + wx * (f11.x - f10.x);
                float byv = f10.y + wx * (f11.y - f10.y);
                float bzv = f10.z + wx * (f11.z - f10.z);
                float bwv = f10.w + wx * (f11.w - f10.w);
                float vx = tx + wy * (bxv - tx);
                float vy = ty + wy * (byv - ty);
                float vz = tz + wy * (bzv - tz);
                float vw = tw + wy * (bwv - tw);
                float dx = f0.x - vx, dy = f0.y - vy, dz = f0.z - vz, dw = f0.w - vw;
                c[k] = dx * dx + dy * dy + dz * dz + dw * dw;
            }
        }

        // butterfly reduce each of the 9 costs across the 8 sublanes
#pragma unroll
        for (int k = 0; k < 9; k++) {
            float vr = c[k];
            vr += __shfl_xor_sync(0xffffffffu, vr, 4);
            vr += __shfl_xor_sync(0xffffffffu, vr, 2);
            vr += __shfl_xor_sync(0xffffffffu, vr, 1);
            c[k] = vr;
        }
        if (s == 0) {
#pragma unroll
            for (int k = 0; k < 9; k++) c_s[li * 9 + k] = c[k];
        }
    }

    __syncthreads();

    // ---------------- Phase B: thread-per-pixel softmax + 6x6 solve ----------------
    {
        const int t = threadIdx.x;
        const int p = base + t;

        float c[9];
#pragma unroll
        for (int k = 0; k < 9; k++) c[k] = c_s[t * 9 + k];

        // softmax(-c): weights
        float m = c[0];
#pragma unroll
        for (int k = 1; k < 9; k++) m = fminf(m, c[k]);
        float wgt[9];
        float sums = 0.f;
#pragma unroll
        for (int k = 0; k < 9; k++) { wgt[k] = __expf(m - c[k]); sums += wgt[k]; }
        const float inv_s = 1.f / sums;
#pragma unroll
        for (int k = 0; k < 9; k++) wgt[k] *= inv_s;

        // Build AtWA (lower triangle, idx(i,j)=i*(i+1)/2+j) and rhs.
        float M[21];
        float r6[6];
#pragma unroll
        for (int i = 0; i < 21; i++) M[i] = 0.f;
#pragma unroll
        for (int i = 0; i < 6; i++) r6[i] = 0.f;
#pragma unroll
        for (int k = 0; k < 9; k++) {
            const float ox = (float)(k % 3 - 1);
            const float oy = (float)(k / 3 - 1);
            const float a[6] = {ox * ox, oy * oy, ox * oy, ox, oy, 1.f};
            const float wk = wgt[k];
            const float wc = wk * c[k];
            int idx = 0;
#pragma unroll
            for (int i = 0; i < 6; i++) {
                r6[i] += a[i] * wc;
#pragma unroll
                for (int j = 0; j <= i; j++) { M[idx] += a[i] * a[j] * wk; idx++; }
            }
        }
        // + EPS * I
        M[0] += EPSR; M[2] += EPSR; M[5] += EPSR; M[9] += EPSR; M[14] += EPSR; M[20] += EPSR;

        // Cholesky factorization (SPD by construction)
        float Lm[21];
        float invd[6];
#pragma unroll
        for (int j = 0; j < 6; j++) {
            float d = M[j * (j + 1) / 2 + j];
#pragma unroll
            for (int k2 = 0; k2 < j; k2++) { float l = Lm[j * (j + 1) / 2 + k2]; d -= l * l; }
            const float iv = rsqrtf(d);
            invd[j] = iv;
            Lm[j * (j + 1) / 2 + j] = d * iv;
#pragma unroll
            for (int i = j + 1; i < 6; i++) {
                float sij = M[i * (i + 1) / 2 + j];
#pragma unroll
                for (int k2 = 0; k2 < j; k2++)
                    sij -= Lm[i * (i + 1) / 2 + k2] * Lm[j * (j + 1) / 2 + k2];
                Lm[i * (i + 1) / 2 + j] = sij * iv;
            }
        }

        // triangular solves: L y = b ; L^T x = y
        float xv[6];
        {
            float yv[6];
#pragma unroll
            for (int i = 0; i < 6; i++) {
                float s2 = r6[i];
#pragma unroll
                for (int k2 = 0; k2 < i; k2++) s2 -= Lm[i * (i + 1) / 2 + k2] * yv[k2];
                yv[i] = s2 * invd[i];
            }
#pragma unroll
            for (int i = 5; i >= 0; i--) {
                float s2 = yv[i];
#pragma unroll
                for (int k2 = i + 1; k2 < 6; k2++) s2 -= Lm[k2 * (k2 + 1) / 2 + i] * xv[k2];
                xv[i] = s2 * invd[i];
            }
        }

        // one iterative-refinement step: x += solve(M, rhs - M x)
        {
            float resid[6];
#pragma unroll
            for (int i = 0; i < 6; i++) {
                float acc = r6[i];
#pragma unroll
                for (int j = 0; j < 6; j++) {
                    const int hi = (i > j) ? i : j;
                    const int lo = (i > j) ? j : i;
                    acc -= M[hi * (hi + 1) / 2 + lo] * xv[j];
                }
                resid[i] = acc;
            }
            float yv[6];
#pragma unroll
            for (int i = 0; i < 6; i++) {
                float s2 = resid[i];
#pragma unroll
                for (int k2 = 0; k2 < i; k2++) s2 -= Lm[i * (i + 1) / 2 + k2] * yv[k2];
                yv[i] = s2 * invd[i];
            }
            float dx[6];
#pragma unroll
            for (int i = 5; i >= 0; i--) {
                float s2 = yv[i];
#pragma unroll
                for (int k2 = i + 1; k2 < 6; k2++) s2 -= Lm[k2 * (k2 + 1) / 2 + i] * dx[k2];
                dx[i] = s2 * invd[i];
            }
#pragma unroll
            for (int i = 0; i < 6; i++) xv[i] += dx[i];
        }

        // p*6 floats is 8-byte aligned -> 3x float2 stores
        float2* op = reinterpret_cast<float2*>(out + (size_t)p * 6);
        op[0] = make_float2(xv[0], xv[1]);
        op[1] = make_float2(xv[2], xv[3]);
        op[2] = make_float2(xv[4], xv[5]);
    }
}

extern "C" void kernel_launch(void* const* d_in, const int* in_sizes, int n_in,
                              void* d_out, int out_size)
{
    const float* feat0 = (const float*)d_in[0];
    const float* feat1 = (const float*)d_in[1];
    const float* flow  = (const float*)d_in[2];
    float* out = (float*)d_out;
    quadfit_kernel<<<(YD * XD) / 256, 256>>>(feat0, feat1, flow, out);
}